// round 14
// baseline (speedup 1.0000x reference)
#include <cuda_runtime.h>
#include <cuda_fp16.h>
#include <math.h>
#include <stdint.h>

// ---------------- problem constants (fixed shapes) ----------------
#define MAXN 50000
#define MAXE 800000
#define FIN  512
#define D1   256      // H1 * C1
#define H1   8
#define C1   32
#define OUTC 64

// ---------------- scratch ----------------
__device__ __half g_xw1h[MAXN * D1];
__device__ float  g_h[MAXN * D1];
__device__ __half g_h2h[MAXN * OUTC];
__device__ float  g_as1[MAXN * H1];
__device__ float  g_ad1[MAXN * H1];
__device__ float  g_as2[MAXN];
__device__ float  g_ad2[MAXN];
__device__ float  g_w1c[FIN * D1];
__device__ float  g_w2c[D1 * OUTC];
__device__ int    g_deg[MAXN];
__device__ int    g_off[MAXN + 1];
__device__ int    g_cur[MAXN];
__device__ int    g_csr[MAXE + MAXN];
__device__ int    g_bsum[64];
__device__ int    g_is64;

__device__ __forceinline__ uint32_t cvt_tf32(uint32_t x) {
    uint32_t r;
    asm("cvt.rna.tf32.f32 %0, %1;" : "=r"(r) : "f"(__uint_as_float(x)));
    return r;
}

// ---------------- weight pre-conversion (rna) ----------------
__global__ void wconv_k(const float* __restrict__ W1, const float* __restrict__ W2) {
    int i = blockIdx.x * blockDim.x + threadIdx.x;
    int n1 = FIN * D1;
    int tot = n1 + D1 * OUTC;
    for (; i < tot; i += gridDim.x * blockDim.x) {
        if (i < n1) g_w1c[i] = __uint_as_float(cvt_tf32(__float_as_uint(W1[i])));
        else        g_w2c[i - n1] = __uint_as_float(cvt_tf32(__float_as_uint(W2[i - n1])));
    }
}

// ---------------- edge dtype detection ----------------
__global__ void detect_k(const unsigned* __restrict__ ew) {
    int t = threadIdx.x;
    unsigned w = ew[2 * t + 1];
    unsigned nz = __ballot_sync(0xffffffffu, w != 0u);
    __shared__ unsigned s[2];
    if ((t & 31) == 0) s[t >> 5] = nz;
    __syncthreads();
    if (t == 0) g_is64 = ((s[0] | s[1]) == 0u) ? 1 : 0;
}

__device__ __forceinline__ int edge_at(const void* ew, int idx) {
    if (g_is64) return (int)((const long long*)ew)[idx];
    return ((const int*)ew)[idx];
}

// ---------------- CSR construction ----------------
__global__ void zero_deg_k(int n) {
    int i = blockIdx.x * blockDim.x + threadIdx.x;
    if (i < n) {
        g_deg[i] = 0;
        g_as2[i] = 0.f;
        g_ad2[i] = 0.f;
    }
}

__global__ void count_deg_k(const void* __restrict__ ew, int E, int N) {
    int e = blockIdx.x * blockDim.x + threadIdx.x;
    int ET = E + N;
    if (e >= ET) return;
    int dst = (e < E) ? edge_at(ew, E + e) : (e - E);
    if ((unsigned)dst < (unsigned)N) atomicAdd(&g_deg[dst], 1);
}

__global__ void scanA_k(int n) {
    __shared__ int s[1024];
    int t = threadIdx.x;
    int i = blockIdx.x * 1024 + t;
    int v = (i < n) ? g_deg[i] : 0;
    s[t] = v;
    __syncthreads();
#pragma unroll
    for (int off = 1; off < 1024; off <<= 1) {
        int tmp = (t >= off) ? s[t - off] : 0;
        __syncthreads();
        s[t] += tmp;
        __syncthreads();
    }
    if (i < n) g_off[i] = s[t] - v;
    if (t == 1023) g_bsum[blockIdx.x] = s[1023];
}

__global__ void scanB_k(int nb, int n) {
    int t = threadIdx.x;
    int v = (t < nb) ? g_bsum[t] : 0;
    int lane = t & 31;
    int incl = v;
#pragma unroll
    for (int off = 1; off < 32; off <<= 1) {
        int u = __shfl_up_sync(0xffffffffu, incl, off);
        if (lane >= off) incl += u;
    }
    __shared__ int wt[2];
    if (lane == 31) wt[t >> 5] = incl;
    __syncthreads();
    int add = (t >= 32) ? wt[0] : 0;
    incl += add;
    if (t < nb) g_bsum[t] = incl - v;
    if (t == 63) g_off[n] = incl;
}

__global__ void scanC_k(int n) {
    int t = threadIdx.x;
    int i = blockIdx.x * 1024 + t;
    if (i < n) {
        int o = g_off[i] + g_bsum[blockIdx.x];
        g_off[i] = o;
        g_cur[i] = o;
    }
}

__global__ void fill_csr_k(const void* __restrict__ ew, int E, int N) {
    int e = blockIdx.x * blockDim.x + threadIdx.x;
    int ET = E + N;
    if (e >= ET) return;
    int src, dst;
    if (e < E) { src = edge_at(ew, e); dst = edge_at(ew, E + e); }
    else       { src = e - E; dst = src; }
    if ((unsigned)dst >= (unsigned)N || (unsigned)src >= (unsigned)N) return;
    int pos = atomicAdd(&g_cur[dst], 1);
    g_csr[pos] = src;
}

// ---------------- TF32 tensor-core GEMM, 3-stage cp.async, 1 barrier/slice ----------------
#define GA_PAD 20

__device__ __forceinline__ void mma_tf32(float* c, const uint32_t* a, const uint32_t* b) {
    asm volatile(
        "mma.sync.aligned.m16n8k8.row.col.f32.tf32.tf32.f32 "
        "{%0,%1,%2,%3}, {%4,%5,%6,%7}, {%8,%9}, {%0,%1,%2,%3};"
        : "+f"(c[0]), "+f"(c[1]), "+f"(c[2]), "+f"(c[3])
        : "r"(a[0]), "r"(a[1]), "r"(a[2]), "r"(a[3]), "r"(b[0]), "r"(b[1]));
}

__device__ __forceinline__ void cp16(uint32_t smem, const float* gptr, bool valid) {
    int sz = valid ? 16 : 0;
    asm volatile("cp.async.cg.shared.global [%0], [%1], 16, %2;"
                 :: "r"(smem), "l"(gptr), "r"(sz));
}

template <int MODE, int BN>
__device__ __forceinline__ void gemm_tf32_body(const float* __restrict__ A,
                                               const float* __restrict__ B,
                                               __half* __restrict__ Ch,
                                               int M, int Nn, int K,
                                               const float* __restrict__ av_src,
                                               const float* __restrict__ av_dst) {
    constexpr int TNT = BN / 16;
    constexpr int GBP = (BN == 128) ? 136 : 72;
    constexpr int NH  = (MODE == 1) ? (BN / 64) : 1;
    constexpr int BF4 = BN / 64;
    constexpr int AS_FLOATS = 128 * GA_PAD;
    constexpr int STAGE_FLOATS = AS_FLOATS + 16 * GBP;

    extern __shared__ float smem_dyn[];

    int tid = threadIdx.x;
    int wid = tid >> 5, lane = tid & 31;
    int lq = lane >> 2, lr = lane & 3;
    int warp_m = wid & 3, warp_n = wid >> 2;
    int row0 = blockIdx.y * 128, col0 = blockIdx.x * BN;
    int wcol = col0 + warp_n * (BN / 2);

    uint32_t sm_base = (uint32_t)__cvta_generic_to_shared(smem_dyn);

    float acc[2][TNT][4];
#pragma unroll
    for (int i = 0; i < 2; i++)
#pragma unroll
        for (int j = 0; j < TNT; j++)
#pragma unroll
            for (int q = 0; q < 4; q++) acc[i][j][q] = 0.f;

    int a_row[2], a_col[2];
#pragma unroll
    for (int u = 0; u < 2; u++) {
        int idx = tid + 256 * u;
        a_row[u] = idx >> 2;
        a_col[u] = (idx & 3) * 4;
    }

    int nk = K >> 4;

    auto issue = [&](int kt, int stage) {
        uint32_t sbase = sm_base + stage * STAGE_FLOATS * 4;
#pragma unroll
        for (int u = 0; u < 2; u++) {
            int r = row0 + a_row[u];
            bool v = (r < M);
            const float* gp = A + (long)(v ? r : 0) * K + (kt << 4) + a_col[u];
            cp16(sbase + (a_row[u] * GA_PAD + a_col[u]) * 4, gp, v);
        }
#pragma unroll
        for (int u = 0; u < BF4; u++) {
            int idx = tid + 256 * u;
            int br = idx / (BN / 4);
            int bc = (idx % (BN / 4)) * 4;
            const float* gp = B + (long)((kt << 4) + br) * Nn + col0 + bc;
            cp16(sbase + (AS_FLOATS + br * GBP + bc) * 4, gp, true);
        }
        asm volatile("cp.async.commit_group;");
    };

    issue(0, 0);
    issue(1, 1);

    int stage = 0;
    for (int kt = 0; kt < nk; kt++) {
        if (kt + 1 < nk) {
            asm volatile("cp.async.wait_group 1;");
        } else {
            asm volatile("cp.async.wait_group 0;");
        }
        __syncthreads();
        // refill the stage consumed 3 iterations ago (all warps passed the sync)
        if (kt + 2 < nk) {
            int ns = stage + 2; if (ns >= 3) ns -= 3;
            issue(kt + 2, ns);
        }

        const float* Asb = smem_dyn + stage * STAGE_FLOATS;
        const float* Bsb = Asb + AS_FLOATS;
#pragma unroll
        for (int kk = 0; kk < 16; kk += 8) {
            uint32_t af[2][4], bf[TNT][2];
#pragma unroll
            for (int tm = 0; tm < 2; tm++) {
                int bm = warp_m * 32 + tm * 16;
                const float* ap = Asb + kk + lr;
                af[tm][0] = cvt_tf32(__float_as_uint(ap[(bm + lq) * GA_PAD]));
                af[tm][1] = cvt_tf32(__float_as_uint(ap[(bm + lq + 8) * GA_PAD]));
                af[tm][2] = cvt_tf32(__float_as_uint(ap[(bm + lq) * GA_PAD + 4]));
                af[tm][3] = cvt_tf32(__float_as_uint(ap[(bm + lq + 8) * GA_PAD + 4]));
            }
#pragma unroll
            for (int tn = 0; tn < TNT; tn++) {
                int bb = warp_n * (BN / 2) + tn * 8 + lq;
                bf[tn][0] = __float_as_uint(Bsb[(kk + lr) * GBP + bb]);
                bf[tn][1] = __float_as_uint(Bsb[(kk + lr + 4) * GBP + bb]);
            }
#pragma unroll
            for (int tm = 0; tm < 2; tm++)
#pragma unroll
                for (int tn = 0; tn < TNT; tn++)
                    mma_tf32(acc[tm][tn], af[tm], bf[tn]);
        }
        if (++stage >= 3) stage = 0;
    }

    // ---- store C as fp16 (half2 pairs) ----
#pragma unroll
    for (int tm = 0; tm < 2; tm++) {
        int r0 = row0 + warp_m * 32 + tm * 16 + lq;
#pragma unroll
        for (int tn = 0; tn < TNT; tn++) {
            int c = wcol + tn * 8 + 2 * lr;
            if (r0 < M) {
                __half2* p = (__half2*)(Ch + (long)r0 * Nn + c);
                *p = __floats2half2_rn(acc[tm][tn][0], acc[tm][tn][1]);
            }
            if (r0 + 8 < M) {
                __half2* p = (__half2*)(Ch + (long)(r0 + 8) * Nn + c);
                *p = __floats2half2_rn(acc[tm][tn][2], acc[tm][tn][3]);
            }
        }
    }

    // ---- fused alpha epilogue ----
    float ps[NH][2][2], pd[NH][2][2];
#pragma unroll
    for (int hl = 0; hl < NH; hl++)
#pragma unroll
        for (int tm = 0; tm < 2; tm++)
#pragma unroll
            for (int hf = 0; hf < 2; hf++) { ps[hl][tm][hf] = 0.f; pd[hl][tm][hf] = 0.f; }

#pragma unroll
    for (int tn = 0; tn < TNT; tn++) {
        int hl = (MODE == 1) ? (tn >> 2) % NH : 0;
        float s0, s1, d0, d1;
        if (MODE == 1) {
            int head = (wcol >> 5) + (tn >> 2);
            int ch = (tn & 3) * 8 + 2 * lr;
            s0 = av_src[head * C1 + ch];     s1 = av_src[head * C1 + ch + 1];
            d0 = av_dst[head * C1 + ch];     d1 = av_dst[head * C1 + ch + 1];
        } else {
            int c = warp_n * (BN / 2) + tn * 8 + 2 * lr;
            s0 = av_src[c]; s1 = av_src[c + 1];
            d0 = av_dst[c]; d1 = av_dst[c + 1];
        }
#pragma unroll
        for (int tm = 0; tm < 2; tm++) {
            ps[hl][tm][0] = fmaf(s0, acc[tm][tn][0], fmaf(s1, acc[tm][tn][1], ps[hl][tm][0]));
            ps[hl][tm][1] = fmaf(s0, acc[tm][tn][2], fmaf(s1, acc[tm][tn][3], ps[hl][tm][1]));
            pd[hl][tm][0] = fmaf(d0, acc[tm][tn][0], fmaf(d1, acc[tm][tn][1], pd[hl][tm][0]));
            pd[hl][tm][1] = fmaf(d0, acc[tm][tn][2], fmaf(d1, acc[tm][tn][3], pd[hl][tm][1]));
        }
    }
#pragma unroll
    for (int hl = 0; hl < NH; hl++)
#pragma unroll
        for (int tm = 0; tm < 2; tm++)
#pragma unroll
            for (int hf = 0; hf < 2; hf++) {
                ps[hl][tm][hf] += __shfl_xor_sync(0xffffffffu, ps[hl][tm][hf], 1);
                ps[hl][tm][hf] += __shfl_xor_sync(0xffffffffu, ps[hl][tm][hf], 2);
                pd[hl][tm][hf] += __shfl_xor_sync(0xffffffffu, pd[hl][tm][hf], 1);
                pd[hl][tm][hf] += __shfl_xor_sync(0xffffffffu, pd[hl][tm][hf], 2);
            }
    if (lr == 0) {
#pragma unroll
        for (int hl = 0; hl < NH; hl++)
#pragma unroll
            for (int tm = 0; tm < 2; tm++)
#pragma unroll
                for (int hf = 0; hf < 2; hf++) {
                    int r = row0 + warp_m * 32 + tm * 16 + lq + hf * 8;
                    if (r < M) {
                        if (MODE == 1) {
                            int head = (wcol >> 5) + hl;
                            g_as1[r * H1 + head] = ps[hl][tm][hf];
                            g_ad1[r * H1 + head] = pd[hl][tm][hf];
                        } else {
                            atomicAdd(&g_as2[r], ps[hl][tm][hf]);
                            atomicAdd(&g_ad2[r], pd[hl][tm][hf]);
                        }
                    }
                }
    }
}

#define GEMM1_SMEM (3 * (128 * GA_PAD + 16 * 136) * 4)
#define GEMM2_SMEM (3 * (128 * GA_PAD + 16 * 72) * 4)

__global__ void gemm1_k(const float* __restrict__ A, int M,
                        const float* __restrict__ av_src, const float* __restrict__ av_dst) {
    gemm_tf32_body<1, 128>(A, g_w1c, g_xw1h, M, D1, FIN, av_src, av_dst);
}
__global__ void gemm2_k(int M,
                        const float* __restrict__ av_src, const float* __restrict__ av_dst) {
    gemm_tf32_body<2, 64>(g_h, g_w2c, g_h2h, M, OUTC, D1, av_src, av_dst);
}

// ---------------- layer-1 aggregation: one WARP per node, 1x LDG.128 per edge ----
__global__ void agg1_k(const float* __restrict__ b1, int N) {
    int warp = (blockIdx.x * blockDim.x + threadIdx.x) >> 5;
    if (warp >= N) return;
    int n = warp;
    int lane = threadIdx.x & 31;
    int beg = g_off[n], end = g_off[n + 1];
    int src_lane = lane >> 2;

    float ad = (lane < H1) ? g_ad1[n * H1 + lane] : 0.f;

    float denom = 0.f;
    float acc[8];
#pragma unroll
    for (int j = 0; j < 8; j++) acc[j] = 0.f;

    int k = beg;
    for (; k + 1 < end; k += 2) {
        int s0 = g_csr[k], s1 = g_csr[k + 1];
        float as0 = (lane < H1) ? g_as1[s0 * H1 + lane] : 0.f;
        float as1v = (lane < H1) ? g_as1[s1 * H1 + lane] : 0.f;
        uint4 p0 = *(const uint4*)(g_xw1h + (long)s0 * D1 + lane * 8);
        uint4 p1 = *(const uint4*)(g_xw1h + (long)s1 * D1 + lane * 8);
        float e0 = as0 + ad; e0 = (e0 > 0.f) ? e0 : 0.2f * e0;
        float e1 = as1v + ad; e1 = (e1 > 0.f) ? e1 : 0.2f * e1;
        float w0 = __expf(e0), w1 = __expf(e1);
        denom += w0;
        float wh0 = __shfl_sync(0xffffffffu, w0, src_lane);
        {
            uint32_t us[4] = {p0.x, p0.y, p0.z, p0.w};
#pragma unroll
            for (int q = 0; q < 4; q++) {
                float2 f = __half22float2(*(__half2*)&us[q]);
                acc[2 * q]     = fmaf(wh0, f.x, acc[2 * q]);
                acc[2 * q + 1] = fmaf(wh0, f.y, acc[2 * q + 1]);
            }
        }
        denom += w1;
        float wh1 = __shfl_sync(0xffffffffu, w1, src_lane);
        {
            uint32_t us[4] = {p1.x, p1.y, p1.z, p1.w};
#pragma unroll
            for (int q = 0; q < 4; q++) {
                float2 f = __half22float2(*(__half2*)&us[q]);
                acc[2 * q]     = fmaf(wh1, f.x, acc[2 * q]);
                acc[2 * q + 1] = fmaf(wh1, f.y, acc[2 * q + 1]);
            }
        }
    }
    if (k < end) {
        int s = g_csr[k];
        float as = (lane < H1) ? g_as1[s * H1 + lane] : 0.f;
        float e = as + ad;
        e = (e > 0.f) ? e : 0.2f * e;
        float w = __expf(e);
        denom += w;
        float wh = __shfl_sync(0xffffffffu, w, src_lane);
        uint4 pkt = *(const uint4*)(g_xw1h + (long)s * D1 + lane * 8);
        uint32_t us[4] = {pkt.x, pkt.y, pkt.z, pkt.w};
#pragma unroll
        for (int q = 0; q < 4; q++) {
            float2 f = __half22float2(*(__half2*)&us[q]);
            acc[2 * q]     = fmaf(wh, f.x, acc[2 * q]);
            acc[2 * q + 1] = fmaf(wh, f.y, acc[2 * q + 1]);
        }
    }
    float inv = 1.f / (denom + 1e-16f);
    float invh = __shfl_sync(0xffffffffu, inv, src_lane);

    float o[8];
#pragma unroll
    for (int j = 0; j < 8; j++) {
        float v = acc[j] * invh + b1[lane * 8 + j];
        o[j] = (v > 0.f) ? v : (__expf(v) - 1.f);
    }
    float4* dst = (float4*)(g_h + (long)n * D1 + lane * 8);
    dst[0] = make_float4(o[0], o[1], o[2], o[3]);
    dst[1] = make_float4(o[4], o[5], o[6], o[7]);
}

// ---------------- layer-2 aggregation + bias + log_softmax ----------------
__global__ void agg2_k(const float* __restrict__ b2, float* __restrict__ out, int N) {
    int warp = (blockIdx.x * blockDim.x + threadIdx.x) >> 5;
    if (warp >= N) return;
    int n = warp;
    int lane = threadIdx.x & 31;
    int beg = g_off[n], end = g_off[n + 1];
    float ad = g_ad2[n];

    float denom = 0.f, a0 = 0.f, a1 = 0.f;
    int k = beg;
    for (; k + 1 < end; k += 2) {
        int s0 = g_csr[k], s1 = g_csr[k + 1];
        float e0 = g_as2[s0] + ad; e0 = (e0 > 0.f) ? e0 : 0.2f * e0;
        float e1 = g_as2[s1] + ad; e1 = (e1 > 0.f) ? e1 : 0.2f * e1;
        __half2 h0 = *(const __half2*)(g_h2h + (long)s0 * OUTC + lane * 2);
        __half2 h1 = *(const __half2*)(g_h2h + (long)s1 * OUTC + lane * 2);
        float w0 = __expf(e0), w1 = __expf(e1);
        float2 f0 = __half22float2(h0), f1 = __half22float2(h1);
        denom += w0;
        a0 = fmaf(w0, f0.x, a0);
        a1 = fmaf(w0, f0.y, a1);
        denom += w1;
        a0 = fmaf(w1, f1.x, a0);
        a1 = fmaf(w1, f1.y, a1);
    }
    if (k < end) {
        int s = g_csr[k];
        float e = g_as2[s] + ad;
        e = (e > 0.f) ? e : 0.2f * e;
        float w = __expf(e);
        denom += w;
        __half2 hv = *(const __half2*)(g_h2h + (long)s * OUTC + lane * 2);
        float2 f = __half22float2(hv);
        a0 = fmaf(w, f.x, a0);
        a1 = fmaf(w, f.y, a1);
    }
    float inv = 1.f / (denom + 1e-16f);
    a0 = a0 * inv + b2[lane * 2];
    a1 = a1 * inv + b2[lane * 2 + 1];

    float mx = fmaxf(a0, a1);
#pragma unroll
    for (int o = 16; o; o >>= 1) mx = fmaxf(mx, __shfl_xor_sync(0xffffffffu, mx, o));
    float sum = __expf(a0 - mx) + __expf(a1 - mx);
#pragma unroll
    for (int o = 16; o; o >>= 1) sum += __shfl_xor_sync(0xffffffffu, sum, o);
    float lse = mx + __logf(sum);
    float2* po = (float2*)(out + (long)n * OUTC + lane * 2);
    *po = make_float2(a0 - lse, a1 - lse);
}

// ---------------- launch ----------------
extern "C" void kernel_launch(void* const* d_in, const int* in_sizes, int n_in,
                              void* d_out, int out_size) {
    const float* x   = (const float*)d_in[0];
    const void*  ei  = d_in[1];
    const float* W1  = (const float*)d_in[2];
    const float* as1 = (const float*)d_in[3];
    const float* ad1 = (const float*)d_in[4];
    const float* b1  = (const float*)d_in[5];
    const float* W2  = (const float*)d_in[6];
    const float* as2 = (const float*)d_in[7];
    const float* ad2 = (const float*)d_in[8];
    const float* b2  = (const float*)d_in[9];
    float* out = (float*)d_out;

    int E = in_sizes[1] / 2;
    int N = in_sizes[0] / FIN;
    int ET = E + N;
    int nb = (N + 1023) / 1024;

    cudaFuncSetAttribute(gemm1_k, cudaFuncAttributeMaxDynamicSharedMemorySize, GEMM1_SMEM);
    cudaFuncSetAttribute(gemm2_k, cudaFuncAttributeMaxDynamicSharedMemorySize, GEMM2_SMEM);

    cudaStream_t s2;
    cudaStreamCreateWithFlags(&s2, cudaStreamNonBlocking);
    cudaEvent_t eFork, eJoin;
    cudaEventCreateWithFlags(&eFork, cudaEventDisableTiming);
    cudaEventCreateWithFlags(&eJoin, cudaEventDisableTiming);

    cudaEventRecord(eFork, 0);
    cudaStreamWaitEvent(s2, eFork, 0);

    wconv_k<<<160, 256>>>(W1, W2);                                   // #1 (default)
    detect_k<<<1, 64, 0, s2>>>((const unsigned*)ei);                 // #2 (s2)
    zero_deg_k<<<(N + 255) / 256, 256, 0, s2>>>(N);                  // #3 (s2)
    {
        dim3 grid(D1 / 128, (N + 127) / 128);
        gemm1_k<<<grid, 256, GEMM1_SMEM>>>(x, N, as1, ad1);          // #4 (default)
    }
    count_deg_k<<<(ET + 255) / 256, 256, 0, s2>>>(ei, E, N);         // #5 (s2)
    scanA_k<<<nb, 1024, 0, s2>>>(N);
    scanB_k<<<1, 64, 0, s2>>>(nb, N);
    scanC_k<<<nb, 1024, 0, s2>>>(N);
    fill_csr_k<<<(ET + 255) / 256, 256, 0, s2>>>(ei, E, N);
    cudaEventRecord(eJoin, s2);

    cudaStreamWaitEvent(0, eJoin, 0);

    agg1_k<<<(N * 32 + 255) / 256, 256>>>(b1, N);
    {
        dim3 grid(OUTC / 64, (N + 127) / 128);
        gemm2_k<<<grid, 256, GEMM2_SMEM>>>(N, as2, ad2);
    }
    agg2_k<<<(N * 32 + 255) / 256, 256>>>(b2, out, N);

    cudaEventDestroy(eFork);
    cudaEventDestroy(eJoin);
    cudaStreamDestroy(s2);
}

// round 15
// speedup vs baseline: 1.0895x; 1.0895x over previous
#include <cuda_runtime.h>
#include <cuda_fp16.h>
#include <math.h>
#include <stdint.h>

// ---------------- problem constants (fixed shapes) ----------------
#define MAXN 50000
#define MAXE 800000
#define FIN  512
#define D1   256      // H1 * C1
#define H1   8
#define C1   32
#define OUTC 64

// ---------------- scratch ----------------
__device__ __align__(16) __half g_xw1h[MAXN * D1];
__device__ __align__(16) float  g_h[MAXN * D1];
__device__ __align__(16) __half g_h2h[MAXN * OUTC];
__device__ float  g_as1[MAXN * H1];
__device__ float  g_ad1[MAXN * H1];
__device__ float  g_as2[MAXN];
__device__ float  g_ad2[MAXN];
__device__ __align__(16) __half g_w1h[D1 * FIN];    // W1^T as fp16: [n][k]
__device__ __align__(16) __half g_w2h[OUTC * D1];   // W2^T as fp16: [n][k]
__device__ int    g_deg[MAXN];
__device__ int    g_off[MAXN + 1];
__device__ int    g_cur[MAXN];
__device__ int    g_csr[MAXE + MAXN];
__device__ int    g_bsum[64];
__device__ int    g_is64;

// ---------------- weight transpose + fp16 conversion ----------------
__global__ void wconv_k(const float* __restrict__ W1, const float* __restrict__ W2) {
    int n1 = D1 * FIN;
    int tot = n1 + OUTC * D1;
    for (int i = blockIdx.x * blockDim.x + threadIdx.x; i < tot; i += gridDim.x * blockDim.x) {
        if (i < n1) {
            int k = i & (FIN - 1), n = i >> 9;
            g_w1h[i] = __float2half_rn(W1[k * D1 + n]);
        } else {
            int j = i - n1;
            int k = j & (D1 - 1), n = j >> 8;
            g_w2h[j] = __float2half_rn(W2[k * OUTC + n]);
        }
    }
}

// ---------------- edge dtype detection ----------------
__global__ void detect_k(const unsigned* __restrict__ ew) {
    int t = threadIdx.x;
    unsigned w = ew[2 * t + 1];
    unsigned nz = __ballot_sync(0xffffffffu, w != 0u);
    __shared__ unsigned s[2];
    if ((t & 31) == 0) s[t >> 5] = nz;
    __syncthreads();
    if (t == 0) g_is64 = ((s[0] | s[1]) == 0u) ? 1 : 0;
}

__device__ __forceinline__ int edge_at(const void* ew, int idx) {
    if (g_is64) return (int)((const long long*)ew)[idx];
    return ((const int*)ew)[idx];
}

// ---------------- CSR construction ----------------
__global__ void zero_deg_k(int n) {
    int i = blockIdx.x * blockDim.x + threadIdx.x;
    if (i < n) {
        g_deg[i] = 0;
        g_as2[i] = 0.f;
        g_ad2[i] = 0.f;
    }
}

__global__ void count_deg_k(const void* __restrict__ ew, int E, int N) {
    int e = blockIdx.x * blockDim.x + threadIdx.x;
    int ET = E + N;
    if (e >= ET) return;
    int dst = (e < E) ? edge_at(ew, E + e) : (e - E);
    if ((unsigned)dst < (unsigned)N) atomicAdd(&g_deg[dst], 1);
}

__global__ void scanA_k(int n) {
    __shared__ int s[1024];
    int t = threadIdx.x;
    int i = blockIdx.x * 1024 + t;
    int v = (i < n) ? g_deg[i] : 0;
    s[t] = v;
    __syncthreads();
#pragma unroll
    for (int off = 1; off < 1024; off <<= 1) {
        int tmp = (t >= off) ? s[t - off] : 0;
        __syncthreads();
        s[t] += tmp;
        __syncthreads();
    }
    if (i < n) g_off[i] = s[t] - v;
    if (t == 1023) g_bsum[blockIdx.x] = s[1023];
}

__global__ void scanB_k(int nb, int n) {
    int t = threadIdx.x;
    int v = (t < nb) ? g_bsum[t] : 0;
    int lane = t & 31;
    int incl = v;
#pragma unroll
    for (int off = 1; off < 32; off <<= 1) {
        int u = __shfl_up_sync(0xffffffffu, incl, off);
        if (lane >= off) incl += u;
    }
    __shared__ int wt[2];
    if (lane == 31) wt[t >> 5] = incl;
    __syncthreads();
    int add = (t >= 32) ? wt[0] : 0;
    incl += add;
    if (t < nb) g_bsum[t] = incl - v;
    if (t == 63) g_off[n] = incl;
}

__global__ void scanC_k(int n) {
    int t = threadIdx.x;
    int i = blockIdx.x * 1024 + t;
    if (i < n) {
        int o = g_off[i] + g_bsum[blockIdx.x];
        g_off[i] = o;
        g_cur[i] = o;
    }
}

__global__ void fill_csr_k(const void* __restrict__ ew, int E, int N) {
    int e = blockIdx.x * blockDim.x + threadIdx.x;
    int ET = E + N;
    if (e >= ET) return;
    int src, dst;
    if (e < E) { src = edge_at(ew, e); dst = edge_at(ew, E + e); }
    else       { src = e - E; dst = src; }
    if ((unsigned)dst >= (unsigned)N || (unsigned)src >= (unsigned)N) return;
    int pos = atomicAdd(&g_cur[dst], 1);
    g_csr[pos] = src;
}

// ---------------- FP16 tensor-core GEMM (m16n8k16), 2-stage cp.async ----------------
// A: fp32 gmem/smem, rounded to fp16 in the fragment pack (rn).
// B: fp16 [n][k] in gmem (pre-transposed weights), k-contiguous.
#define ASTRIDE 20         // floats per A smem row (16 data + 4 pad)
#define BSTRIDE_W 12       // uint32 words per B smem col (16 halves + 8 pad)

__device__ __forceinline__ void mma_f16(float* c, const uint32_t* a, const uint32_t* b) {
    asm volatile(
        "mma.sync.aligned.m16n8k16.row.col.f32.f16.f16.f32 "
        "{%0,%1,%2,%3}, {%4,%5,%6,%7}, {%8,%9}, {%0,%1,%2,%3};"
        : "+f"(c[0]), "+f"(c[1]), "+f"(c[2]), "+f"(c[3])
        : "r"(a[0]), "r"(a[1]), "r"(a[2]), "r"(a[3]), "r"(b[0]), "r"(b[1]));
}

__device__ __forceinline__ void cp16(uint32_t smem, const void* gptr, bool valid) {
    int sz = valid ? 16 : 0;
    asm volatile("cp.async.cg.shared.global [%0], [%1], 16, %2;"
                 :: "r"(smem), "l"(gptr), "r"(sz));
}

__device__ __forceinline__ uint32_t packh2(float x, float y) {
    __half2 h = __floats2half2_rn(x, y);
    return *(uint32_t*)&h;
}

template <int MODE, int BN>
__device__ __forceinline__ void gemm_fp16_body(const float* __restrict__ A,
                                               const __half* __restrict__ Bw,
                                               __half* __restrict__ Ch,
                                               int M, int Nn, int K,
                                               const float* __restrict__ av_src,
                                               const float* __restrict__ av_dst) {
    constexpr int TNT = BN / 16;              // n-tiles of 8 per warp
    constexpr int NH  = (MODE == 1) ? (BN / 64) : 1;
    constexpr int AS_FLOATS = 128 * ASTRIDE;
    constexpr int BS_WORDS  = BN * BSTRIDE_W;

    __shared__ float    As[2][AS_FLOATS];
    __shared__ uint32_t Bs[2][BS_WORDS];

    int tid = threadIdx.x;
    int wid = tid >> 5, lane = tid & 31;
    int lq = lane >> 2, lr = lane & 3;
    int warp_m = wid & 3, warp_n = wid >> 2;
    int row0 = blockIdx.y * 128, col0 = blockIdx.x * BN;
    int wcol = col0 + warp_n * (BN / 2);

    uint32_t as_base = (uint32_t)__cvta_generic_to_shared(&As[0][0]);
    uint32_t bs_base = (uint32_t)__cvta_generic_to_shared(&Bs[0][0]);

    float acc[2][TNT][4];
#pragma unroll
    for (int i = 0; i < 2; i++)
#pragma unroll
        for (int j = 0; j < TNT; j++)
#pragma unroll
            for (int q = 0; q < 4; q++) acc[i][j][q] = 0.f;

    int a_row[2], a_col[2];
#pragma unroll
    for (int u = 0; u < 2; u++) {
        int idx = tid + 256 * u;
        a_row[u] = idx >> 2;
        a_col[u] = (idx & 3) * 4;
    }

    int nk = K >> 4;

    auto issue = [&](int kt, int stage) {
        // A tile 128x16 fp32 (zfill OOB rows)
#pragma unroll
        for (int u = 0; u < 2; u++) {
            int r = row0 + a_row[u];
            bool v = (r < M);
            const float* gp = A + (long)(v ? r : 0) * K + (kt << 4) + a_col[u];
            cp16(as_base + (stage * AS_FLOATS + a_row[u] * ASTRIDE + a_col[u]) * 4, gp, v);
        }
        // B tile BN cols x 16 halves (k-contiguous); 2 chunks per col
        {
            int idx = tid;
            if (idx < BN * 2) {
                int col = idx >> 1;
                int hoff = (idx & 1) * 8;
                const __half* gp = Bw + (long)(col0 + col) * K + (kt << 4) + hoff;
                cp16(bs_base + (stage * BS_WORDS + col * BSTRIDE_W + (hoff >> 1)) * 4, gp, true);
            }
        }
        asm volatile("cp.async.commit_group;");
    };

    issue(0, 0);

    for (int kt = 0; kt < nk; kt++) {
        int stage = kt & 1;
        if (kt + 1 < nk) {
            issue(kt + 1, stage ^ 1);
            asm volatile("cp.async.wait_group 1;");
        } else {
            asm volatile("cp.async.wait_group 0;");
        }
        __syncthreads();

        const float* Asb = &As[stage][0];
        const uint32_t* Bsb = &Bs[stage][0];

        uint32_t af[2][4], bf[TNT][2];
#pragma unroll
        for (int tm = 0; tm < 2; tm++) {
            int bm = warp_m * 32 + tm * 16;
            const float* r0p = Asb + (bm + lq) * ASTRIDE + 2 * lr;
            const float* r1p = Asb + (bm + lq + 8) * ASTRIDE + 2 * lr;
            float2 f00 = *(const float2*)(r0p);
            float2 f01 = *(const float2*)(r0p + 8);
            float2 f10 = *(const float2*)(r1p);
            float2 f11 = *(const float2*)(r1p + 8);
            af[tm][0] = packh2(f00.x, f00.y);
            af[tm][1] = packh2(f10.x, f10.y);
            af[tm][2] = packh2(f01.x, f01.y);
            af[tm][3] = packh2(f11.x, f11.y);
        }
#pragma unroll
        for (int tn = 0; tn < TNT; tn++) {
            int bb = warp_n * (BN / 2) + tn * 8 + lq;
            bf[tn][0] = Bsb[bb * BSTRIDE_W + lr];
            bf[tn][1] = Bsb[bb * BSTRIDE_W + lr + 4];
        }
#pragma unroll
        for (int tm = 0; tm < 2; tm++)
#pragma unroll
            for (int tn = 0; tn < TNT; tn++)
                mma_f16(acc[tm][tn], af[tm], bf[tn]);

        __syncthreads();
    }

    // ---- store C as fp16 (half2 pairs) ----
#pragma unroll
    for (int tm = 0; tm < 2; tm++) {
        int r0 = row0 + warp_m * 32 + tm * 16 + lq;
#pragma unroll
        for (int tn = 0; tn < TNT; tn++) {
            int c = wcol + tn * 8 + 2 * lr;
            if (r0 < M) {
                __half2* p = (__half2*)(Ch + (long)r0 * Nn + c);
                *p = __floats2half2_rn(acc[tm][tn][0], acc[tm][tn][1]);
            }
            if (r0 + 8 < M) {
                __half2* p = (__half2*)(Ch + (long)(r0 + 8) * Nn + c);
                *p = __floats2half2_rn(acc[tm][tn][2], acc[tm][tn][3]);
            }
        }
    }

    // ---- fused alpha epilogue (fp32 accumulators) ----
    float ps[NH][2][2], pd[NH][2][2];
#pragma unroll
    for (int hl = 0; hl < NH; hl++)
#pragma unroll
        for (int tm = 0; tm < 2; tm++)
#pragma unroll
            for (int hf = 0; hf < 2; hf++) { ps[hl][tm][hf] = 0.f; pd[hl][tm][hf] = 0.f; }

#pragma unroll
    for (int tn = 0; tn < TNT; tn++) {
        int hl = (MODE == 1) ? (tn >> 2) % NH : 0;
        float s0, s1, d0, d1;
        if (MODE == 1) {
            int head = (wcol >> 5) + (tn >> 2);
            int ch = (tn & 3) * 8 + 2 * lr;
            s0 = av_src[head * C1 + ch];     s1 = av_src[head * C1 + ch + 1];
            d0 = av_dst[head * C1 + ch];     d1 = av_dst[head * C1 + ch + 1];
        } else {
            int c = warp_n * (BN / 2) + tn * 8 + 2 * lr;
            s0 = av_src[c]; s1 = av_src[c + 1];
            d0 = av_dst[c]; d1 = av_dst[c + 1];
        }
#pragma unroll
        for (int tm = 0; tm < 2; tm++) {
            ps[hl][tm][0] = fmaf(s0, acc[tm][tn][0], fmaf(s1, acc[tm][tn][1], ps[hl][tm][0]));
            ps[hl][tm][1] = fmaf(s0, acc[tm][tn][2], fmaf(s1, acc[tm][tn][3], ps[hl][tm][1]));
            pd[hl][tm][0] = fmaf(d0, acc[tm][tn][0], fmaf(d1, acc[tm][tn][1], pd[hl][tm][0]));
            pd[hl][tm][1] = fmaf(d0, acc[tm][tn][2], fmaf(d1, acc[tm][tn][3], pd[hl][tm][1]));
        }
    }
#pragma unroll
    for (int hl = 0; hl < NH; hl++)
#pragma unroll
        for (int tm = 0; tm < 2; tm++)
#pragma unroll
            for (int hf = 0; hf < 2; hf++) {
                ps[hl][tm][hf] += __shfl_xor_sync(0xffffffffu, ps[hl][tm][hf], 1);
                ps[hl][tm][hf] += __shfl_xor_sync(0xffffffffu, ps[hl][tm][hf], 2);
                pd[hl][tm][hf] += __shfl_xor_sync(0xffffffffu, pd[hl][tm][hf], 1);
                pd[hl][tm][hf] += __shfl_xor_sync(0xffffffffu, pd[hl][tm][hf], 2);
            }
    if (lr == 0) {
#pragma unroll
        for (int hl = 0; hl < NH; hl++)
#pragma unroll
            for (int tm = 0; tm < 2; tm++)
#pragma unroll
                for (int hf = 0; hf < 2; hf++) {
                    int r = row0 + warp_m * 32 + tm * 16 + lq + hf * 8;
                    if (r < M) {
                        if (MODE == 1) {
                            int head = (wcol >> 5) + hl;
                            g_as1[r * H1 + head] = ps[hl][tm][hf];
                            g_ad1[r * H1 + head] = pd[hl][tm][hf];
                        } else {
                            atomicAdd(&g_as2[r], ps[hl][tm][hf]);
                            atomicAdd(&g_ad2[r], pd[hl][tm][hf]);
                        }
                    }
                }
    }
}

__global__ __launch_bounds__(256, 2)
void gemm1_k(const float* __restrict__ A, int M,
             const float* __restrict__ av_src, const float* __restrict__ av_dst) {
    gemm_fp16_body<1, 128>(A, g_w1h, g_xw1h, M, D1, FIN, av_src, av_dst);
}
__global__ __launch_bounds__(256, 2)
void gemm2_k(int M,
             const float* __restrict__ av_src, const float* __restrict__ av_dst) {
    gemm_fp16_body<2, 64>(g_h, g_w2h, g_h2h, M, OUTC, D1, av_src, av_dst);
}

// ---------------- layer-1 aggregation: one WARP per node, 1x LDG.128 per edge ----
__global__ void agg1_k(const float* __restrict__ b1, int N) {
    int warp = (blockIdx.x * blockDim.x + threadIdx.x) >> 5;
    if (warp >= N) return;
    int n = warp;
    int lane = threadIdx.x & 31;
    int beg = g_off[n], end = g_off[n + 1];
    int src_lane = lane >> 2;

    float ad = (lane < H1) ? g_ad1[n * H1 + lane] : 0.f;

    float denom = 0.f;
    float acc[8];
#pragma unroll
    for (int j = 0; j < 8; j++) acc[j] = 0.f;

    int k = beg;
    for (; k + 1 < end; k += 2) {
        int s0 = g_csr[k], s1 = g_csr[k + 1];
        float as0 = (lane < H1) ? g_as1[s0 * H1 + lane] : 0.f;
        float as1v = (lane < H1) ? g_as1[s1 * H1 + lane] : 0.f;
        uint4 p0 = *(const uint4*)(g_xw1h + (long)s0 * D1 + lane * 8);
        uint4 p1 = *(const uint4*)(g_xw1h + (long)s1 * D1 + lane * 8);
        float e0 = as0 + ad; e0 = (e0 > 0.f) ? e0 : 0.2f * e0;
        float e1 = as1v + ad; e1 = (e1 > 0.f) ? e1 : 0.2f * e1;
        float w0 = __expf(e0), w1 = __expf(e1);
        denom += w0;
        float wh0 = __shfl_sync(0xffffffffu, w0, src_lane);
        {
            uint32_t us[4] = {p0.x, p0.y, p0.z, p0.w};
#pragma unroll
            for (int q = 0; q < 4; q++) {
                float2 f = __half22float2(*(__half2*)&us[q]);
                acc[2 * q]     = fmaf(wh0, f.x, acc[2 * q]);
                acc[2 * q + 1] = fmaf(wh0, f.y, acc[2 * q + 1]);
            }
        }
        denom += w1;
        float wh1 = __shfl_sync(0xffffffffu, w1, src_lane);
        {
            uint32_t us[4] = {p1.x, p1.y, p1.z, p1.w};
#pragma unroll
            for (int q = 0; q < 4; q++) {
                float2 f = __half22float2(*(__half2*)&us[q]);
                acc[2 * q]     = fmaf(wh1, f.x, acc[2 * q]);
                acc[2 * q + 1] = fmaf(wh1, f.y, acc[2 * q + 1]);
            }
        }
    }
    if (k < end) {
        int s = g_csr[k];
        float as = (lane < H1) ? g_as1[s * H1 + lane] : 0.f;
        float e = as + ad;
        e = (e > 0.f) ? e : 0.2f * e;
        float w = __expf(e);
        denom += w;
        float wh = __shfl_sync(0xffffffffu, w, src_lane);
        uint4 pkt = *(const uint4*)(g_xw1h + (long)s * D1 + lane * 8);
        uint32_t us[4] = {pkt.x, pkt.y, pkt.z, pkt.w};
#pragma unroll
        for (int q = 0; q < 4; q++) {
            float2 f = __half22float2(*(__half2*)&us[q]);
            acc[2 * q]     = fmaf(wh, f.x, acc[2 * q]);
            acc[2 * q + 1] = fmaf(wh, f.y, acc[2 * q + 1]);
        }
    }
    float inv = 1.f / (denom + 1e-16f);
    float invh = __shfl_sync(0xffffffffu, inv, src_lane);

    float o[8];
#pragma unroll
    for (int j = 0; j < 8; j++) {
        float v = acc[j] * invh + b1[lane * 8 + j];
        o[j] = (v > 0.f) ? v : (__expf(v) - 1.f);
    }
    float4* dst = (float4*)(g_h + (long)n * D1 + lane * 8);
    dst[0] = make_float4(o[0], o[1], o[2], o[3]);
    dst[1] = make_float4(o[4], o[5], o[6], o[7]);
}

// ---------------- layer-2 aggregation + bias + log_softmax ----------------
__global__ void agg2_k(const float* __restrict__ b2, float* __restrict__ out, int N) {
    int warp = (blockIdx.x * blockDim.x + threadIdx.x) >> 5;
    if (warp >= N) return;
    int n = warp;
    int lane = threadIdx.x & 31;
    int beg = g_off[n], end = g_off[n + 1];
    float ad = g_ad2[n];

    float denom = 0.f, a0 = 0.f, a1 = 0.f;
    int k = beg;
    for (; k + 1 < end; k += 2) {
        int s0 = g_csr[k], s1 = g_csr[k + 1];
        float e0 = g_as2[s0] + ad; e0 = (e0 > 0.f) ? e0 : 0.2f * e0;
        float e1 = g_as2[s1] + ad; e1 = (e1 > 0.f) ? e1 : 0.2f * e1;
        __half2 h0 = *(const __half2*)(g_h2h + (long)s0 * OUTC + lane * 2);
        __half2 h1 = *(const __half2*)(g_h2h + (long)s1 * OUTC + lane * 2);
        float w0 = __expf(e0), w1 = __expf(e1);
        float2 f0 = __half22float2(h0), f1 = __half22float2(h1);
        denom += w0;
        a0 = fmaf(w0, f0.x, a0);
        a1 = fmaf(w0, f0.y, a1);
        denom += w1;
        a0 = fmaf(w1, f1.x, a0);
        a1 = fmaf(w1, f1.y, a1);
    }
    if (k < end) {
        int s = g_csr[k];
        float e = g_as2[s] + ad;
        e = (e > 0.f) ? e : 0.2f * e;
        float w = __expf(e);
        denom += w;
        __half2 hv = *(const __half2*)(g_h2h + (long)s * OUTC + lane * 2);
        float2 f = __half22float2(hv);
        a0 = fmaf(w, f.x, a0);
        a1 = fmaf(w, f.y, a1);
    }
    float inv = 1.f / (denom + 1e-16f);
    a0 = a0 * inv + b2[lane * 2];
    a1 = a1 * inv + b2[lane * 2 + 1];

    float mx = fmaxf(a0, a1);
#pragma unroll
    for (int o = 16; o; o >>= 1) mx = fmaxf(mx, __shfl_xor_sync(0xffffffffu, mx, o));
    float sum = __expf(a0 - mx) + __expf(a1 - mx);
#pragma unroll
    for (int o = 16; o; o >>= 1) sum += __shfl_xor_sync(0xffffffffu, sum, o);
    float lse = mx + __logf(sum);
    float2* po = (float2*)(out + (long)n * OUTC + lane * 2);
    *po = make_float2(a0 - lse, a1 - lse);
}

// ---------------- launch ----------------
extern "C" void kernel_launch(void* const* d_in, const int* in_sizes, int n_in,
                              void* d_out, int out_size) {
    const float* x   = (const float*)d_in[0];
    const void*  ei  = d_in[1];
    const float* W1  = (const float*)d_in[2];
    const float* as1 = (const float*)d_in[3];
    const float* ad1 = (const float*)d_in[4];
    const float* b1  = (const float*)d_in[5];
    const float* W2  = (const float*)d_in[6];
    const float* as2 = (const float*)d_in[7];
    const float* ad2 = (const float*)d_in[8];
    const float* b2  = (const float*)d_in[9];
    float* out = (float*)d_out;

    int E = in_sizes[1] / 2;
    int N = in_sizes[0] / FIN;
    int ET = E + N;
    int nb = (N + 1023) / 1024;

    cudaStream_t s2;
    cudaStreamCreateWithFlags(&s2, cudaStreamNonBlocking);
    cudaEvent_t eFork, eJoin;
    cudaEventCreateWithFlags(&eFork, cudaEventDisableTiming);
    cudaEventCreateWithFlags(&eJoin, cudaEventDisableTiming);

    cudaEventRecord(eFork, 0);
    cudaStreamWaitEvent(s2, eFork, 0);

    wconv_k<<<160, 256>>>(W1, W2);                                   // #1 (default)
    detect_k<<<1, 64, 0, s2>>>((const unsigned*)ei);                 // #2 (s2)
    zero_deg_k<<<(N + 255) / 256, 256, 0, s2>>>(N);                  // #3 (s2)
    {
        dim3 grid(D1 / 128, (N + 127) / 128);
        gemm1_k<<<grid, 256>>>(x, N, as1, ad1);                      // #4 (default)
    }
    count_deg_k<<<(ET + 255) / 256, 256, 0, s2>>>(ei, E, N);         // #5 (s2)
    scanA_k<<<nb, 1024, 0, s2>>>(N);
    scanB_k<<<1, 64, 0, s2>>>(nb, N);
    scanC_k<<<nb, 1024, 0, s2>>>(N);
    fill_csr_k<<<(ET + 255) / 256, 256, 0, s2>>>(ei, E, N);
    cudaEventRecord(eJoin, s2);

    cudaStreamWaitEvent(0, eJoin, 0);

    agg1_k<<<(N * 32 + 255) / 256, 256>>>(b1, N);
    {
        dim3 grid(OUTC / 64, (N + 127) / 128);
        gemm2_k<<<grid, 256>>>(N, as2, ad2);
    }
    agg2_k<<<(N * 32 + 255) / 256, 256>>>(b2, out, N);

    cudaEventDestroy(eFork);
    cudaEventDestroy(eJoin);
    cudaStreamDestroy(s2);
}

// round 16
// speedup vs baseline: 1.1712x; 1.0750x over previous
#include <cuda_runtime.h>
#include <cuda_fp16.h>
#include <math.h>
#include <stdint.h>

// ---------------- problem constants (fixed shapes) ----------------
#define MAXN 50000
#define MAXE 800000
#define FIN  512
#define D1   256      // H1 * C1
#define H1   8
#define C1   32
#define OUTC 64

// ---------------- scratch ----------------
__device__ __align__(16) __half g_xw1h[MAXN * D1];
__device__ __align__(16) float  g_h[MAXN * D1];
__device__ __align__(16) __half g_h2h[MAXN * OUTC];
__device__ float  g_as1[MAXN * H1];
__device__ float  g_ad1[MAXN * H1];
__device__ float  g_as2[MAXN];
__device__ float  g_ad2[MAXN];
__device__ __align__(16) __half g_w1h[D1 * FIN];    // W1^T as fp16: [n][k]
__device__ __align__(16) __half g_w2h[OUTC * D1];   // W2^T as fp16: [n][k]
__device__ int    g_deg[MAXN];
__device__ int    g_off[MAXN + 1];
__device__ int    g_cur[MAXN];
__device__ int    g_csr[MAXE + MAXN];
__device__ int    g_bsum[64];
__device__ int    g_is64;

// ---------------- weight transpose + fp16 conversion ----------------
__global__ void wconv_k(const float* __restrict__ W1, const float* __restrict__ W2) {
    int n1 = D1 * FIN;
    int tot = n1 + OUTC * D1;
    for (int i = blockIdx.x * blockDim.x + threadIdx.x; i < tot; i += gridDim.x * blockDim.x) {
        if (i < n1) {
            int k = i & (FIN - 1), n = i >> 9;
            g_w1h[i] = __float2half_rn(W1[k * D1 + n]);
        } else {
            int j = i - n1;
            int k = j & (D1 - 1), n = j >> 8;
            g_w2h[j] = __float2half_rn(W2[k * OUTC + n]);
        }
    }
}

// ---------------- edge dtype detection ----------------
__global__ void detect_k(const unsigned* __restrict__ ew) {
    int t = threadIdx.x;
    unsigned w = ew[2 * t + 1];
    unsigned nz = __ballot_sync(0xffffffffu, w != 0u);
    __shared__ unsigned s[2];
    if ((t & 31) == 0) s[t >> 5] = nz;
    __syncthreads();
    if (t == 0) g_is64 = ((s[0] | s[1]) == 0u) ? 1 : 0;
}

__device__ __forceinline__ int edge_at(const void* ew, int idx) {
    if (g_is64) return (int)((const long long*)ew)[idx];
    return ((const int*)ew)[idx];
}

// ---------------- CSR construction ----------------
__global__ void zero_deg_k(int n) {
    int i = blockIdx.x * blockDim.x + threadIdx.x;
    if (i < n) {
        g_deg[i] = 0;
        g_as2[i] = 0.f;
        g_ad2[i] = 0.f;
    }
}

__global__ void count_deg_k(const void* __restrict__ ew, int E, int N) {
    int e = blockIdx.x * blockDim.x + threadIdx.x;
    int ET = E + N;
    if (e >= ET) return;
    int dst = (e < E) ? edge_at(ew, E + e) : (e - E);
    if ((unsigned)dst < (unsigned)N) atomicAdd(&g_deg[dst], 1);
}

__global__ void scanA_k(int n) {
    __shared__ int s[1024];
    int t = threadIdx.x;
    int i = blockIdx.x * 1024 + t;
    int v = (i < n) ? g_deg[i] : 0;
    s[t] = v;
    __syncthreads();
#pragma unroll
    for (int off = 1; off < 1024; off <<= 1) {
        int tmp = (t >= off) ? s[t - off] : 0;
        __syncthreads();
        s[t] += tmp;
        __syncthreads();
    }
    if (i < n) g_off[i] = s[t] - v;
    if (t == 1023) g_bsum[blockIdx.x] = s[1023];
}

__global__ void scanB_k(int nb, int n) {
    int t = threadIdx.x;
    int v = (t < nb) ? g_bsum[t] : 0;
    int lane = t & 31;
    int incl = v;
#pragma unroll
    for (int off = 1; off < 32; off <<= 1) {
        int u = __shfl_up_sync(0xffffffffu, incl, off);
        if (lane >= off) incl += u;
    }
    __shared__ int wt[2];
    if (lane == 31) wt[t >> 5] = incl;
    __syncthreads();
    int add = (t >= 32) ? wt[0] : 0;
    incl += add;
    if (t < nb) g_bsum[t] = incl - v;
    if (t == 63) g_off[n] = incl;
}

__global__ void scanC_k(int n) {
    int t = threadIdx.x;
    int i = blockIdx.x * 1024 + t;
    if (i < n) {
        int o = g_off[i] + g_bsum[blockIdx.x];
        g_off[i] = o;
        g_cur[i] = o;
    }
}

__global__ void fill_csr_k(const void* __restrict__ ew, int E, int N) {
    int e = blockIdx.x * blockDim.x + threadIdx.x;
    int ET = E + N;
    if (e >= ET) return;
    int src, dst;
    if (e < E) { src = edge_at(ew, e); dst = edge_at(ew, E + e); }
    else       { src = e - E; dst = src; }
    if ((unsigned)dst >= (unsigned)N || (unsigned)src >= (unsigned)N) return;
    int pos = atomicAdd(&g_cur[dst], 1);
    g_csr[pos] = src;
}

// ---------------- FP16 tensor-core GEMM (m16n8k16), BK=32, 2-stage cp.async ----------------
#define ASTRIDE 36         // floats per A smem row (32 data + 4 pad)
#define BSW     20         // uint32 words per B smem col (16 data + 4 pad)

__device__ __forceinline__ void mma_f16(float* c, const uint32_t* a, const uint32_t* b) {
    asm volatile(
        "mma.sync.aligned.m16n8k16.row.col.f32.f16.f16.f32 "
        "{%0,%1,%2,%3}, {%4,%5,%6,%7}, {%8,%9}, {%0,%1,%2,%3};"
        : "+f"(c[0]), "+f"(c[1]), "+f"(c[2]), "+f"(c[3])
        : "r"(a[0]), "r"(a[1]), "r"(a[2]), "r"(a[3]), "r"(b[0]), "r"(b[1]));
}

__device__ __forceinline__ void cp16(uint32_t smem, const void* gptr, bool valid) {
    int sz = valid ? 16 : 0;
    asm volatile("cp.async.cg.shared.global [%0], [%1], 16, %2;"
                 :: "r"(smem), "l"(gptr), "r"(sz));
}

__device__ __forceinline__ uint32_t packh2(float x, float y) {
    __half2 h = __floats2half2_rn(x, y);
    return *(uint32_t*)&h;
}

template <int MODE, int BN>
__device__ __forceinline__ void gemm_fp16_body(const float* __restrict__ A,
                                               const __half* __restrict__ Bw,
                                               __half* __restrict__ Ch,
                                               int M, int Nn, int K,
                                               const float* __restrict__ av_src,
                                               const float* __restrict__ av_dst) {
    constexpr int TNT = BN / 16;
    constexpr int NH  = (MODE == 1) ? (BN / 64) : 1;
    constexpr int AS_FLOATS = 128 * ASTRIDE;           // per stage
    constexpr int BS_WORDS  = BN * BSW;                // per stage
    constexpr int BCH = BN / 64;                       // B 16B-chunk loads per thread

    extern __shared__ float smem_dyn[];
    float*    As = smem_dyn;                           // [2][AS_FLOATS]
    uint32_t* Bs = (uint32_t*)(smem_dyn + 2 * AS_FLOATS);  // [2][BS_WORDS]

    int tid = threadIdx.x;
    int wid = tid >> 5, lane = tid & 31;
    int lq = lane >> 2, lr = lane & 3;
    int warp_m = wid & 3, warp_n = wid >> 2;
    int row0 = blockIdx.y * 128, col0 = blockIdx.x * BN;
    int wcol = col0 + warp_n * (BN / 2);

    uint32_t as_base = (uint32_t)__cvta_generic_to_shared(As);
    uint32_t bs_base = (uint32_t)__cvta_generic_to_shared(Bs);

    float acc[2][TNT][4];
#pragma unroll
    for (int i = 0; i < 2; i++)
#pragma unroll
        for (int j = 0; j < TNT; j++)
#pragma unroll
            for (int q = 0; q < 4; q++) acc[i][j][q] = 0.f;

    // A: 128x32 floats = 1024 float4 per tile -> 4 per thread
    int a_row[4], a_col[4];
#pragma unroll
    for (int u = 0; u < 4; u++) {
        int idx = tid + 256 * u;
        a_row[u] = idx >> 3;
        a_col[u] = (idx & 7) * 4;
    }

    int nk = K >> 5;

    auto issue = [&](int kt, int stage) {
#pragma unroll
        for (int u = 0; u < 4; u++) {
            int r = row0 + a_row[u];
            bool v = (r < M);
            const float* gp = A + (long)(v ? r : 0) * K + (kt << 5) + a_col[u];
            cp16(as_base + (stage * AS_FLOATS + a_row[u] * ASTRIDE + a_col[u]) * 4, gp, v);
        }
        // B: BN cols x 32 halves = BN*4 chunks of 8 halves
#pragma unroll
        for (int u = 0; u < BCH; u++) {
            int idx = tid + 256 * u;
            int col = idx >> 2;
            int hoff = (idx & 3) * 8;
            const __half* gp = Bw + (long)(col0 + col) * K + (kt << 5) + hoff;
            cp16(bs_base + (stage * BS_WORDS + col * BSW + (hoff >> 1)) * 4, gp, true);
        }
        asm volatile("cp.async.commit_group;");
    };

    issue(0, 0);

    for (int kt = 0; kt < nk; kt++) {
        int stage = kt & 1;
        if (kt + 1 < nk) {
            issue(kt + 1, stage ^ 1);
            asm volatile("cp.async.wait_group 1;");
        } else {
            asm volatile("cp.async.wait_group 0;");
        }
        __syncthreads();

        const float* Asb = As + stage * AS_FLOATS;
        const uint32_t* Bsb = Bs + stage * BS_WORDS;

#pragma unroll
        for (int ks = 0; ks < 2; ks++) {
            uint32_t af[2][4], bf[TNT][2];
#pragma unroll
            for (int tm = 0; tm < 2; tm++) {
                int bm = warp_m * 32 + tm * 16;
                const float* r0p = Asb + (bm + lq) * ASTRIDE + ks * 16 + 2 * lr;
                const float* r1p = Asb + (bm + lq + 8) * ASTRIDE + ks * 16 + 2 * lr;
                float2 f00 = *(const float2*)(r0p);
                float2 f01 = *(const float2*)(r0p + 8);
                float2 f10 = *(const float2*)(r1p);
                float2 f11 = *(const float2*)(r1p + 8);
                af[tm][0] = packh2(f00.x, f00.y);
                af[tm][1] = packh2(f10.x, f10.y);
                af[tm][2] = packh2(f01.x, f01.y);
                af[tm][3] = packh2(f11.x, f11.y);
            }
#pragma unroll
            for (int tn = 0; tn < TNT; tn++) {
                int bb = warp_n * (BN / 2) + tn * 8 + lq;
                bf[tn][0] = Bsb[bb * BSW + ks * 8 + lr];
                bf[tn][1] = Bsb[bb * BSW + ks * 8 + lr + 4];
            }
#pragma unroll
            for (int tm = 0; tm < 2; tm++)
#pragma unroll
                for (int tn = 0; tn < TNT; tn++)
                    mma_f16(acc[tm][tn], af[tm], bf[tn]);
        }
        __syncthreads();
    }

    // ---- store C as fp16 (half2 pairs) ----
#pragma unroll
    for (int tm = 0; tm < 2; tm++) {
        int r0 = row0 + warp_m * 32 + tm * 16 + lq;
#pragma unroll
        for (int tn = 0; tn < TNT; tn++) {
            int c = wcol + tn * 8 + 2 * lr;
            if (r0 < M) {
                __half2* p = (__half2*)(Ch + (long)r0 * Nn + c);
                *p = __floats2half2_rn(acc[tm][tn][0], acc[tm][tn][1]);
            }
            if (r0 + 8 < M) {
                __half2* p = (__half2*)(Ch + (long)(r0 + 8) * Nn + c);
                *p = __floats2half2_rn(acc[tm][tn][2], acc[tm][tn][3]);
            }
        }
    }

    // ---- fused alpha epilogue (fp32 accumulators) ----
    float ps[NH][2][2], pd[NH][2][2];
#pragma unroll
    for (int hl = 0; hl < NH; hl++)
#pragma unroll
        for (int tm = 0; tm < 2; tm++)
#pragma unroll
            for (int hf = 0; hf < 2; hf++) { ps[hl][tm][hf] = 0.f; pd[hl][tm][hf] = 0.f; }

#pragma unroll
    for (int tn = 0; tn < TNT; tn++) {
        int hl = (MODE == 1) ? (tn >> 2) % NH : 0;
        float s0, s1, d0, d1;
        if (MODE == 1) {
            int head = (wcol >> 5) + (tn >> 2);
            int ch = (tn & 3) * 8 + 2 * lr;
            s0 = av_src[head * C1 + ch];     s1 = av_src[head * C1 + ch + 1];
            d0 = av_dst[head * C1 + ch];     d1 = av_dst[head * C1 + ch + 1];
        } else {
            int c = warp_n * (BN / 2) + tn * 8 + 2 * lr;
            s0 = av_src[c]; s1 = av_src[c + 1];
            d0 = av_dst[c]; d1 = av_dst[c + 1];
        }
#pragma unroll
        for (int tm = 0; tm < 2; tm++) {
            ps[hl][tm][0] = fmaf(s0, acc[tm][tn][0], fmaf(s1, acc[tm][tn][1], ps[hl][tm][0]));
            ps[hl][tm][1] = fmaf(s0, acc[tm][tn][2], fmaf(s1, acc[tm][tn][3], ps[hl][tm][1]));
            pd[hl][tm][0] = fmaf(d0, acc[tm][tn][0], fmaf(d1, acc[tm][tn][1], pd[hl][tm][0]));
            pd[hl][tm][1] = fmaf(d0, acc[tm][tn][2], fmaf(d1, acc[tm][tn][3], pd[hl][tm][1]));
        }
    }
#pragma unroll
    for (int hl = 0; hl < NH; hl++)
#pragma unroll
        for (int tm = 0; tm < 2; tm++)
#pragma unroll
            for (int hf = 0; hf < 2; hf++) {
                ps[hl][tm][hf] += __shfl_xor_sync(0xffffffffu, ps[hl][tm][hf], 1);
                ps[hl][tm][hf] += __shfl_xor_sync(0xffffffffu, ps[hl][tm][hf], 2);
                pd[hl][tm][hf] += __shfl_xor_sync(0xffffffffu, pd[hl][tm][hf], 1);
                pd[hl][tm][hf] += __shfl_xor_sync(0xffffffffu, pd[hl][tm][hf], 2);
            }
    if (lr == 0) {
#pragma unroll
        for (int hl = 0; hl < NH; hl++)
#pragma unroll
            for (int tm = 0; tm < 2; tm++)
#pragma unroll
                for (int hf = 0; hf < 2; hf++) {
                    int r = row0 + warp_m * 32 + tm * 16 + lq + hf * 8;
                    if (r < M) {
                        if (MODE == 1) {
                            int head = (wcol >> 5) + hl;
                            g_as1[r * H1 + head] = ps[hl][tm][hf];
                            g_ad1[r * H1 + head] = pd[hl][tm][hf];
                        } else {
                            atomicAdd(&g_as2[r], ps[hl][tm][hf]);
                            atomicAdd(&g_ad2[r], pd[hl][tm][hf]);
                        }
                    }
                }
    }
}

#define GEMM1_SMEM ((2 * 128 * ASTRIDE + 2 * 128 * BSW) * 4)
#define GEMM2_SMEM ((2 * 128 * ASTRIDE + 2 * 64 * BSW) * 4)

__global__ __launch_bounds__(256, 2)
void gemm1_k(const float* __restrict__ A, int M,
             const float* __restrict__ av_src, const float* __restrict__ av_dst) {
    gemm_fp16_body<1, 128>(A, g_w1h, g_xw1h, M, D1, FIN, av_src, av_dst);
}
__global__ __launch_bounds__(256, 2)
void gemm2_k(int M,
             const float* __restrict__ av_src, const float* __restrict__ av_dst) {
    gemm_fp16_body<2, 64>(g_h, g_w2h, g_h2h, M, OUTC, D1, av_src, av_dst);
}

// ---------------- layer-1 aggregation: one WARP per node, 1x LDG.128 per edge ----
__global__ void agg1_k(const float* __restrict__ b1, int N) {
    int warp = (blockIdx.x * blockDim.x + threadIdx.x) >> 5;
    if (warp >= N) return;
    int n = warp;
    int lane = threadIdx.x & 31;
    int beg = g_off[n], end = g_off[n + 1];
    int src_lane = lane >> 2;

    float ad = (lane < H1) ? g_ad1[n * H1 + lane] : 0.f;

    float denom = 0.f;
    float acc[8];
#pragma unroll
    for (int j = 0; j < 8; j++) acc[j] = 0.f;

    int k = beg;
    for (; k + 1 < end; k += 2) {
        int s0 = g_csr[k], s1 = g_csr[k + 1];
        float as0 = (lane < H1) ? g_as1[s0 * H1 + lane] : 0.f;
        float as1v = (lane < H1) ? g_as1[s1 * H1 + lane] : 0.f;
        uint4 p0 = *(const uint4*)(g_xw1h + (long)s0 * D1 + lane * 8);
        uint4 p1 = *(const uint4*)(g_xw1h + (long)s1 * D1 + lane * 8);
        float e0 = as0 + ad; e0 = (e0 > 0.f) ? e0 : 0.2f * e0;
        float e1 = as1v + ad; e1 = (e1 > 0.f) ? e1 : 0.2f * e1;
        float w0 = __expf(e0), w1 = __expf(e1);
        denom += w0;
        float wh0 = __shfl_sync(0xffffffffu, w0, src_lane);
        {
            uint32_t us[4] = {p0.x, p0.y, p0.z, p0.w};
#pragma unroll
            for (int q = 0; q < 4; q++) {
                float2 f = __half22float2(*(__half2*)&us[q]);
                acc[2 * q]     = fmaf(wh0, f.x, acc[2 * q]);
                acc[2 * q + 1] = fmaf(wh0, f.y, acc[2 * q + 1]);
            }
        }
        denom += w1;
        float wh1 = __shfl_sync(0xffffffffu, w1, src_lane);
        {
            uint32_t us[4] = {p1.x, p1.y, p1.z, p1.w};
#pragma unroll
            for (int q = 0; q < 4; q++) {
                float2 f = __half22float2(*(__half2*)&us[q]);
                acc[2 * q]     = fmaf(wh1, f.x, acc[2 * q]);
                acc[2 * q + 1] = fmaf(wh1, f.y, acc[2 * q + 1]);
            }
        }
    }
    if (k < end) {
        int s = g_csr[k];
        float as = (lane < H1) ? g_as1[s * H1 + lane] : 0.f;
        float e = as + ad;
        e = (e > 0.f) ? e : 0.2f * e;
        float w = __expf(e);
        denom += w;
        float wh = __shfl_sync(0xffffffffu, w, src_lane);
        uint4 pkt = *(const uint4*)(g_xw1h + (long)s * D1 + lane * 8);
        uint32_t us[4] = {pkt.x, pkt.y, pkt.z, pkt.w};
#pragma unroll
        for (int q = 0; q < 4; q++) {
            float2 f = __half22float2(*(__half2*)&us[q]);
            acc[2 * q]     = fmaf(wh, f.x, acc[2 * q]);
            acc[2 * q + 1] = fmaf(wh, f.y, acc[2 * q + 1]);
        }
    }
    float inv = 1.f / (denom + 1e-16f);
    float invh = __shfl_sync(0xffffffffu, inv, src_lane);

    float o[8];
#pragma unroll
    for (int j = 0; j < 8; j++) {
        float v = acc[j] * invh + b1[lane * 8 + j];
        o[j] = (v > 0.f) ? v : (__expf(v) - 1.f);
    }
    float4* dst = (float4*)(g_h + (long)n * D1 + lane * 8);
    dst[0] = make_float4(o[0], o[1], o[2], o[3]);
    dst[1] = make_float4(o[4], o[5], o[6], o[7]);
}

// ---------------- layer-2 aggregation + bias + log_softmax ----------------
__global__ void agg2_k(const float* __restrict__ b2, float* __restrict__ out, int N) {
    int warp = (blockIdx.x * blockDim.x + threadIdx.x) >> 5;
    if (warp >= N) return;
    int n = warp;
    int lane = threadIdx.x & 31;
    int beg = g_off[n], end = g_off[n + 1];
    float ad = g_ad2[n];

    float denom = 0.f, a0 = 0.f, a1 = 0.f;
    int k = beg;
    for (; k + 1 < end; k += 2) {
        int s0 = g_csr[k], s1 = g_csr[k + 1];
        float e0 = g_as2[s0] + ad; e0 = (e0 > 0.f) ? e0 : 0.2f * e0;
        float e1 = g_as2[s1] + ad; e1 = (e1 > 0.f) ? e1 : 0.2f * e1;
        __half2 h0 = *(const __half2*)(g_h2h + (long)s0 * OUTC + lane * 2);
        __half2 h1 = *(const __half2*)(g_h2h + (long)s1 * OUTC + lane * 2);
        float w0 = __expf(e0), w1 = __expf(e1);
        float2 f0 = __half22float2(h0), f1 = __half22float2(h1);
        denom += w0;
        a0 = fmaf(w0, f0.x, a0);
        a1 = fmaf(w0, f0.y, a1);
        denom += w1;
        a0 = fmaf(w1, f1.x, a0);
        a1 = fmaf(w1, f1.y, a1);
    }
    if (k < end) {
        int s = g_csr[k];
        float e = g_as2[s] + ad;
        e = (e > 0.f) ? e : 0.2f * e;
        float w = __expf(e);
        denom += w;
        __half2 hv = *(const __half2*)(g_h2h + (long)s * OUTC + lane * 2);
        float2 f = __half22float2(hv);
        a0 = fmaf(w, f.x, a0);
        a1 = fmaf(w, f.y, a1);
    }
    float inv = 1.f / (denom + 1e-16f);
    a0 = a0 * inv + b2[lane * 2];
    a1 = a1 * inv + b2[lane * 2 + 1];

    float mx = fmaxf(a0, a1);
#pragma unroll
    for (int o = 16; o; o >>= 1) mx = fmaxf(mx, __shfl_xor_sync(0xffffffffu, mx, o));
    float sum = __expf(a0 - mx) + __expf(a1 - mx);
#pragma unroll
    for (int o = 16; o; o >>= 1) sum += __shfl_xor_sync(0xffffffffu, sum, o);
    float lse = mx + __logf(sum);
    float2* po = (float2*)(out + (long)n * OUTC + lane * 2);
    *po = make_float2(a0 - lse, a1 - lse);
}

// ---------------- launch ----------------
extern "C" void kernel_launch(void* const* d_in, const int* in_sizes, int n_in,
                              void* d_out, int out_size) {
    const float* x   = (const float*)d_in[0];
    const void*  ei  = d_in[1];
    const float* W1  = (const float*)d_in[2];
    const float* as1 = (const float*)d_in[3];
    const float* ad1 = (const float*)d_in[4];
    const float* b1  = (const float*)d_in[5];
    const float* W2  = (const float*)d_in[6];
    const float* as2 = (const float*)d_in[7];
    const float* ad2 = (const float*)d_in[8];
    const float* b2  = (const float*)d_in[9];
    float* out = (float*)d_out;

    int E = in_sizes[1] / 2;
    int N = in_sizes[0] / FIN;
    int ET = E + N;
    int nb = (N + 1023) / 1024;

    cudaFuncSetAttribute(gemm1_k, cudaFuncAttributeMaxDynamicSharedMemorySize, GEMM1_SMEM);
    cudaFuncSetAttribute(gemm2_k, cudaFuncAttributeMaxDynamicSharedMemorySize, GEMM2_SMEM);

    cudaStream_t s2;
    cudaStreamCreateWithFlags(&s2, cudaStreamNonBlocking);
    cudaEvent_t eFork, eJoin;
    cudaEventCreateWithFlags(&eFork, cudaEventDisableTiming);
    cudaEventCreateWithFlags(&eJoin, cudaEventDisableTiming);

    cudaEventRecord(eFork, 0);
    cudaStreamWaitEvent(s2, eFork, 0);

    wconv_k<<<160, 256>>>(W1, W2);                                   // #1 (default)
    detect_k<<<1, 64, 0, s2>>>((const unsigned*)ei);                 // #2 (s2)
    zero_deg_k<<<(N + 255) / 256, 256, 0, s2>>>(N);                  // #3 (s2)
    {
        dim3 grid(D1 / 128, (N + 127) / 128);
        gemm1_k<<<grid, 256, GEMM1_SMEM>>>(x, N, as1, ad1);          // #4 (default)
    }
    count_deg_k<<<(ET + 255) / 256, 256, 0, s2>>>(ei, E, N);         // #5 (s2)
    scanA_k<<<nb, 1024, 0, s2>>>(N);
    scanB_k<<<1, 64, 0, s2>>>(nb, N);
    scanC_k<<<nb, 1024, 0, s2>>>(N);
    fill_csr_k<<<(ET + 255) / 256, 256, 0, s2>>>(ei, E, N);
    cudaEventRecord(eJoin, s2);

    cudaStreamWaitEvent(0, eJoin, 0);

    agg1_k<<<(N * 32 + 255) / 256, 256>>>(b1, N);
    {
        dim3 grid(OUTC / 64, (N + 127) / 128);
        gemm2_k<<<grid, 256, GEMM2_SMEM>>>(N, as2, ad2);
    }
    agg2_k<<<(N * 32 + 255) / 256, 256>>>(b2, out, N);

    cudaEventDestroy(eFork);
    cudaEventDestroy(eJoin);
    cudaStreamDestroy(s2);
}